// round 7
// baseline (speedup 1.0000x reference)
#include <cuda_runtime.h>
#include <cuda_bf16.h>
#include <cstdint>

// Problem constants
#define BATCH 32
#define CIN 8
#define COUT 8
#define DIN 16
#define DOUT 16
#define HW 1024            // 32*32
#define OC_TOTAL 1024      // CIN*COUT*DOUT
#define EPSV 1e-5f

// ---------------- scratch (device globals; no allocation allowed) ----------------
__device__ __align__(16) float g_votes [BATCH*OC_TOTAL*HW];   // 128 MB [b][oc][u][v]
__device__ float g_pooled[BATCH*COUT*2*DOUT*HW];              // 64 MB
__device__ float g_rbuf  [BATCH*COUT*DOUT*HW];                // 16 MB
__device__ float g_gate  [BATCH*COUT*DOUT*HW];                // 16 MB
__device__ float g_bnacc [16];
__device__ float g_bnAB  [16];

// ---------------- packed f32x2 helpers ----------------
typedef unsigned long long u64;
__device__ __forceinline__ u64 pk2(float lo, float hi){
    u64 r; asm("mov.b64 %0, {%1,%2};" : "=l"(r) : "f"(lo), "f"(hi)); return r;
}
__device__ __forceinline__ void upk2(u64 v, float& lo, float& hi){
    asm("mov.b64 {%0,%1}, %2;" : "=f"(lo), "=f"(hi) : "l"(v));
}
__device__ __forceinline__ u64 ffma2(u64 a, u64 b, u64 c){
    u64 d; asm("fma.rn.f32x2 %0, %1, %2, %3;" : "=l"(d) : "l"(a), "l"(b), "l"(c)); return d;
}

__device__ __forceinline__ uint32_t smem_to_u32(const void* p) {
    uint32_t a;
    asm("{ .reg .u64 t; cvta.to.shared.u64 t, %1; cvt.u32.u64 %0, t; }" : "=r"(a) : "l"(p));
    return a;
}

// ---------------- mma.sync helpers (sm_80-compatible PTX, no 'a' features) ----------------
#define LDSM4(r0, r1, r2, r3, addr) \
    asm volatile("ldmatrix.sync.aligned.m8n8.x4.shared.b16 {%0,%1,%2,%3}, [%4];" \
                 : "=r"(r0), "=r"(r1), "=r"(r2), "=r"(r3) : "r"(addr))

#define MMA_BF16(acc, a, b) \
    asm volatile("mma.sync.aligned.m16n8k16.row.col.f32.bf16.bf16.f32 " \
                 "{%0,%1,%2,%3}, {%4,%5,%6,%7}, {%8,%9}, {%0,%1,%2,%3};" \
                 : "+f"((acc)[0]), "+f"((acc)[1]), "+f"((acc)[2]), "+f"((acc)[3]) \
                 : "r"((a)[0]), "r"((a)[1]), "r"((a)[2]), "r"((a)[3]), \
                   "r"((b)[0]), "r"((b)[1]))

// bf16 two-term split: x ~= hi + lo, residual ~2^-18 |x|
__device__ __forceinline__ void bsplit(float x, unsigned short& h, unsigned short& l){
    __nv_bfloat16 bh = __float2bfloat16(x);
    float r = x - __bfloat162float(bh);
    __nv_bfloat16 bl = __float2bfloat16(r);
    h = __bfloat16_as_ushort(bh);
    l = __bfloat16_as_ushort(bl);
}

// Chunked swizzle: row stride 384B = 3 x 128B chunks; XOR confined to a 128B chunk.
__device__ __forceinline__ uint32_t swz(uint32_t row, uint32_t kbyte){
    return row*384u + (kbyte & ~127u) + ((kbyte & 127u) ^ ((row & 7u) << 4));
}

// ---------------- K0: zero BN accumulators ----------------
__global__ void k0_zero(){
    if (threadIdx.x < 16) g_bnacc[threadIdx.x] = 0.f;
}

// ---------------- K1: conv2d via bf16-split mma.sync tensor-core GEMM ----------------
// CTA = (octile of 128 oc, utile of 4 u-rows, b). GEMM: M=128 (oc), N=128 (pos),
// K=144 (din*9 taps). A = W split into (A1,A2) bf16; B = im2col split (B1,B2).
// D = A1B1 + A2B1 + A1B2 (3xBF16 compensation). 8 warps as 2(m)x4(n); warp tile 64x32.
// smem rows: 384B stride (3 x 128B chunks), per-chunk XOR swizzle => conflict-free ldmatrix.
#define K1_AB_BYTES (128*384)              // 49152
#define K1_SM_STAGE 0                      // 16*6*34 floats = 13056 B
#define K1_SM_A1    13312
#define K1_SM_A2    (K1_SM_A1 + K1_AB_BYTES)   // 62464
#define K1_SM_B1    (K1_SM_A2 + K1_AB_BYTES)   // 111616
#define K1_SM_B2    (K1_SM_B1 + K1_AB_BYTES)   // 160768
#define K1_SMEM     (K1_SM_B2 + K1_AB_BYTES)   // 209920

__global__ __launch_bounds__(256, 1) void k1_conv2d(
        const float* __restrict__ caps, const float* __restrict__ Wt,
        const float* __restrict__ bt){
    extern __shared__ __align__(16) char smem[];
    uint32_t smem_u32 = smem_to_u32(smem);
    float* stage = (float*)(smem + K1_SM_STAGE);

    int octile = blockIdx.x;             // 0..7  -> ocbase = octile*128
    int utile  = blockIdx.y;             // 0..7  -> u0 = utile*4
    int b      = blockIdx.z;             // 0..31
    int tid  = threadIdx.x;
    int wid  = tid >> 5;
    int lane = tid & 31;
    int ocbase = octile * 128;
    int u0 = utile * 4;

    // ---- stage padded caps tile [din 16][6 rows][34 cols] (u0-1 .. u0+4) ----
    const float* cb = caps + (size_t)b * (DIN*HW);
    for (int i = tid; i < 16*6*34; i += 256){
        int din = i / 204;
        int rem = i - din*204;
        int ur = rem / 34, vx = rem - ur*34;
        int u = u0 + ur - 1, v = vx - 1;
        float x = 0.f;
        if ((unsigned)u < 32u && (unsigned)v < 32u) x = cb[din*HW + u*32 + v];
        stage[i] = x;
    }

    // ---- A split: W tile [m 128][k 144] -> A1/A2 bf16, chunk-swizzled ----
    const float* wb = Wt + (size_t)ocbase * 144;
    for (int i = tid; i < 128*72; i += 256){
        int m = i / 72, k2 = i - m*72;
        float2 w = ((const float2*)(wb + m*144))[k2];
        unsigned short h0, l0, h1, l1;
        bsplit(w.x, h0, l0);
        bsplit(w.y, h1, l1);
        uint32_t off = swz((uint32_t)m, (uint32_t)(k2*4));
        *(uint32_t*)(smem + K1_SM_A1 + off) = (uint32_t)h0 | ((uint32_t)h1 << 16);
        *(uint32_t*)(smem + K1_SM_A2 + off) = (uint32_t)l0 | ((uint32_t)l1 << 16);
    }
    __syncthreads();   // stage ready before im2col

    // ---- B split: im2col Bt [n 128][k 144] -> B1/B2 bf16, chunk-swizzled ----
    for (int i = tid; i < 128*72; i += 256){
        int n = i / 72, k2 = i - n*72;
        int k = k2*2;
        int ur = n >> 5, v = n & 31;
        int din0 = k / 9,     tap0 = k - din0*9;
        int din1 = (k+1) / 9, tap1 = (k+1) - din1*9;
        float x0 = stage[din0*204 + (ur + tap0/3)*34 + (v + tap0%3)];
        float x1 = stage[din1*204 + (ur + tap1/3)*34 + (v + tap1%3)];
        unsigned short h0, l0, h1, l1;
        bsplit(x0, h0, l0);
        bsplit(x1, h1, l1);
        uint32_t off = swz((uint32_t)n, (uint32_t)(k2*4));
        *(uint32_t*)(smem + K1_SM_B1 + off) = (uint32_t)h0 | ((uint32_t)h1 << 16);
        *(uint32_t*)(smem + K1_SM_B2 + off) = (uint32_t)l0 | ((uint32_t)l1 << 16);
    }
    __syncthreads();

    // ---- main mma loop ----
    int wm = wid & 1;       // m half (64 rows)
    int wn = wid >> 1;      // n quarter (32 cols)

    float acc[4][4][4];
    #pragma unroll
    for (int mf = 0; mf < 4; mf++)
        #pragma unroll
        for (int nf = 0; nf < 4; nf++)
            #pragma unroll
            for (int r = 0; r < 4; r++) acc[mf][nf][r] = 0.f;

    // A fragment lane mapping: row = base + (lane&15), k+8 selected by lane bit4
    uint32_t a_lr  = (uint32_t)(lane & 15);
    uint32_t a_kq = (uint32_t)((lane >> 4) << 4);       // +16B if lane>=16
    // B fragment lane mapping (from Bt): row = base + (lane&7) + 8*(bit4), k+8 by bit3
    uint32_t b_lr  = (uint32_t)((lane & 7) | ((lane & 16) >> 1));
    uint32_t b_kq = (uint32_t)((lane & 8) << 1);        // +16B if bit3

    uint32_t aRow[4], bRow[2];
    #pragma unroll
    for (int mf = 0; mf < 4; mf++) aRow[mf] = (uint32_t)(wm*64 + mf*16) + a_lr;
    #pragma unroll
    for (int nf2 = 0; nf2 < 2; nf2++) bRow[nf2] = (uint32_t)(wn*32 + nf2*16) + b_lr;

    uint32_t sA1 = smem_u32 + K1_SM_A1, sA2 = smem_u32 + K1_SM_A2;
    uint32_t sB1 = smem_u32 + K1_SM_B1, sB2 = smem_u32 + K1_SM_B2;

    #pragma unroll
    for (int kk = 0; kk < 9; kk++){
        uint32_t kbA = (uint32_t)(kk*32) + a_kq;   // byte offset of k0 (+lane k select)
        uint32_t kbB = (uint32_t)(kk*32) + b_kq;

        uint32_t afr[4][4], b1f[4][2], b2f[4][2];

        // load A1 frags
        #pragma unroll
        for (int mf = 0; mf < 4; mf++)
            LDSM4(afr[mf][0], afr[mf][1], afr[mf][2], afr[mf][3],
                  sA1 + swz(aRow[mf], kbA));
        // load B1 + B2 frags
        #pragma unroll
        for (int nf2 = 0; nf2 < 2; nf2++){
            uint32_t t0,t1,t2,t3;
            LDSM4(t0,t1,t2,t3, sB1 + swz(bRow[nf2], kbB));
            b1f[nf2*2][0]=t0; b1f[nf2*2][1]=t1; b1f[nf2*2+1][0]=t2; b1f[nf2*2+1][1]=t3;
            LDSM4(t0,t1,t2,t3, sB2 + swz(bRow[nf2], kbB));
            b2f[nf2*2][0]=t0; b2f[nf2*2][1]=t1; b2f[nf2*2+1][0]=t2; b2f[nf2*2+1][1]=t3;
        }
        // A1*B1 and A1*B2
        #pragma unroll
        for (int mf = 0; mf < 4; mf++)
            #pragma unroll
            for (int nf = 0; nf < 4; nf++){
                MMA_BF16(acc[mf][nf], afr[mf], b1f[nf]);
                MMA_BF16(acc[mf][nf], afr[mf], b2f[nf]);
            }
        // load A2 frags (reuse regs), A2*B1
        #pragma unroll
        for (int mf = 0; mf < 4; mf++)
            LDSM4(afr[mf][0], afr[mf][1], afr[mf][2], afr[mf][3],
                  sA2 + swz(aRow[mf], kbA));
        #pragma unroll
        for (int mf = 0; mf < 4; mf++)
            #pragma unroll
            for (int nf = 0; nf < 4; nf++)
                MMA_BF16(acc[mf][nf], afr[mf], b1f[nf]);
    }

    // ---- epilogue: add bias, store to votes ----
    int g = lane >> 2, q = lane & 3;
    float* vbase = g_votes + (size_t)b*(OC_TOTAL*HW);
    #pragma unroll
    for (int mf = 0; mf < 4; mf++){
        int r0 = ocbase + wm*64 + mf*16 + g;
        int r1 = r0 + 8;
        float bias0 = __ldg(bt + r0);
        float bias1 = __ldg(bt + r1);
        #pragma unroll
        for (int nf = 0; nf < 4; nf++){
            int n = utile*128 + wn*32 + nf*8 + q*2;
            float2 v0 = { acc[mf][nf][0] + bias0, acc[mf][nf][1] + bias0 };
            float2 v1 = { acc[mf][nf][2] + bias1, acc[mf][nf][3] + bias1 };
            *(float2*)(vbase + (size_t)r0*HW + n) = v0;
            *(float2*)(vbase + (size_t)r1*HW + n) = v1;
        }
    }
}

// ---------------- K2: values + pooled(max/mean) + routing result r ----------------
__global__ __launch_bounds__(256) void k2_values(
        const float* __restrict__ Wv, const float* __restrict__ bv){
    __shared__ __align__(16) float sWv[256];   // [c][m]
    __shared__ float sBv[32];
    int b = blockIdx.z, o = blockIdx.y;
    int tid = threadIdx.x;
    int pos = blockIdx.x*256 + tid;

    { int m = tid >> 3, c = tid & 7; sWv[c*32 + m] = Wv[o*256 + tid]; }
    if (tid < 32) sBv[tid] = bv[o*32 + tid];
    __syncthreads();

    int d = pos >> 10, uv = pos & 1023;
    const float* vp = g_votes + (size_t)b*(OC_TOTAL*HW) + (size_t)(o*16 + d)*HW + uv;
    float vc[8];
    #pragma unroll
    for (int c = 0; c < 8; c++) vc[c] = vp[(size_t)c*128*HW];

    u64 acc[16];
    #pragma unroll
    for (int mp = 0; mp < 16; mp++) acc[mp] = pk2(sBv[2*mp], sBv[2*mp+1]);
    #pragma unroll
    for (int c = 0; c < 8; c++){
        u64 x = pk2(vc[c], vc[c]);
        const u64* wp = (const u64*)(sWv + c*32);
        #pragma unroll
        for (int mp = 0; mp < 16; mp++) acc[mp] = ffma2(wp[mp], x, acc[mp]);
    }
    float val[32];
    #pragma unroll
    for (int mp = 0; mp < 16; mp++) upk2(acc[mp], val[2*mp], val[2*mp+1]);

    float mx = val[0], sm = val[0];
    #pragma unroll
    for (int m = 1; m < 32; m++){ mx = fmaxf(mx, val[m]); sm += val[m]; }
    size_t pbase = (size_t)((b*8 + o)*2)*(DOUT*HW) + pos;
    g_pooled[pbase]           = mx;
    g_pooled[pbase + DOUT*HW] = sm * (1.f/32.f);

    float rnum = 0.f, rden = 0.f;
    #pragma unroll
    for (int c = 0; c < 8; c++){
        float a0 = val[c], a1 = val[c+8], a2 = val[c+16], a3 = val[c+24];
        float s1 = a0+a1+a2+a3;
        float s2 = a0*a0 + a1*a1 + a2*a2 + a3*a3;
        float mu  = s1 * 0.25f;
        float var = s2 * 0.25f - mu*mu;
        float sd  = sqrtf(fmaxf(var, 0.f));
        float wgt = 1.f / sd;
        rden += wgt; rnum += wgt * mu;
    }
    g_rbuf[(size_t)(b*8 + o)*(DOUT*HW) + pos] = rnum / rden;
}

// ---------------- K3: conv3d gate + BN partial sums ----------------
#define K3_T (2*18*10*34)
__global__ __launch_bounds__(256) void k3_conv3d(const float* __restrict__ Ws){
    extern __shared__ float sT[];
    __shared__ float sWs[54];
    __shared__ float sred[16];
    int ut = blockIdx.x, o = blockIdx.y, b = blockIdx.z;
    int tid = threadIdx.x;
    if (tid < 54) sWs[tid] = Ws[tid];
    const float* pb = g_pooled + (size_t)(b*8 + o)*2*(DOUT*HW);
    int u0 = ut*8;
    for (int idx = tid; idx < K3_T; idx += 256){
        int vx = idx % 34; int r1 = idx / 34;
        int uy = r1 % 10;  int r2 = r1 / 10;
        int dz = r2 % 18;  int i  = r2 / 18;
        int d = dz - 1, u = u0 + uy - 1, v = vx - 1;
        float x = 0.f;
        if ((unsigned)d < 16u && (unsigned)u < 32u && (unsigned)v < 32u)
            x = pb[i*(DOUT*HW) + d*HW + u*32 + v];
        sT[idx] = x;
    }
    __syncthreads();

    int ul = tid >> 5, v = tid & 31;
    float acc[16];
    #pragma unroll
    for (int dI = 0; dI < 16; dI++) acc[dI] = 0.f;

    #pragma unroll
    for (int dd = 0; dd < 18; dd++){
        float t[18];
        #pragma unroll
        for (int i = 0; i < 2; i++)
            #pragma unroll
            for (int dy = 0; dy < 3; dy++)
                #pragma unroll
                for (int dx = 0; dx < 3; dx++)
                    t[i*9 + dy*3 + dx] = sT[((i*18 + dd)*10 + ul + dy)*34 + v + dx];
        #pragma unroll
        for (int dz = 0; dz < 3; dz++){
            int dO = dd - dz;
            if (dO >= 0 && dO < 16){
                float a = acc[dO];
                #pragma unroll
                for (int i = 0; i < 2; i++)
                    #pragma unroll
                    for (int dy = 0; dy < 3; dy++)
                        #pragma unroll
                        for (int dx = 0; dx < 3; dx++)
                            a += t[i*9 + dy*3 + dx] * sWs[(i*3 + dz)*9 + dy*3 + dx];
                acc[dO] = a;
            }
        }
    }

    float s = 0.f, q = 0.f;
    float* gb = g_gate + (size_t)(b*8 + o)*(DOUT*HW) + (u0 + ul)*32 + v;
    #pragma unroll
    for (int dI = 0; dI < 16; dI++){
        gb[dI*HW] = acc[dI];
        s += acc[dI]; q += acc[dI]*acc[dI];
    }
    #pragma unroll
    for (int off = 16; off; off >>= 1){
        s += __shfl_xor_sync(0xffffffffu, s, off);
        q += __shfl_xor_sync(0xffffffffu, q, off);
    }
    if ((tid & 31) == 0){ sred[tid>>5] = s; sred[8 + (tid>>5)] = q; }
    __syncthreads();
    if (tid == 0){
        float S = 0.f, Q = 0.f;
        for (int i = 0; i < 8; i++){ S += sred[i]; Q += sred[8+i]; }
        atomicAdd(&g_bnacc[o],     S);
        atomicAdd(&g_bnacc[8 + o], Q);
    }
}

// ---------------- K4: finalize BN affine ----------------
__global__ void k4_bn(const float* __restrict__ bng, const float* __restrict__ bnb){
    int o = threadIdx.x;
    if (o < 8){
        const float n = (float)(BATCH*DOUT*HW);
        float mu  = g_bnacc[o] / n;
        float var = g_bnacc[8+o] / n - mu*mu;
        float A = bng[0] / sqrtf(var + EPSV);
        g_bnAB[o]     = A;
        g_bnAB[8 + o] = bnb[0] - mu*A;
    }
}

// ---------------- K5: gate*routing + LayerNorm + transposed write ----------------
__global__ __launch_bounds__(256) void k5_final(
        const float* __restrict__ lng, const float* __restrict__ lnb,
        float* __restrict__ out){
    extern __shared__ float scn[];
    __shared__ float sred[16];
    __shared__ float sMV[2];
    int b = blockIdx.x, o = blockIdx.y;
    int tid = threadIdx.x;
    float A = g_bnAB[o], Bb = g_bnAB[8 + o];
    const float* gg = g_gate + (size_t)(b*8 + o)*16384;
    const float* rr = g_rbuf + (size_t)(b*8 + o)*16384;
    float s = 0.f, q = 0.f;
    #pragma unroll 8
    for (int j = 0; j < 64; j++){
        int p = tid + j*256;
        float gn = gg[p]*A + Bb;
        float sc = 1.f + 1.f/(1.f + expf(-gn));
        float cn = rr[p] * sc;
        scn[p] = cn; s += cn; q += cn*cn;
    }
    #pragma unroll
    for (int off = 16; off; off >>= 1){
        s += __shfl_xor_sync(0xffffffffu, s, off);
        q += __shfl_xor_sync(0xffffffffu, q, off);
    }
    if ((tid & 31) == 0){ sred[tid>>5] = s; sred[8 + (tid>>5)] = q; }
    __syncthreads();
    if (tid == 0){
        float S = 0.f, Q = 0.f;
        for (int i = 0; i < 8; i++){ S += sred[i]; Q += sred[8+i]; }
        float mean = S * (1.f/16384.f);
        float var  = Q * (1.f/16384.f) - mean*mean;
        sMV[0] = mean;
        sMV[1] = 1.f / sqrtf(var + EPSV);
    }
    __syncthreads();
    float mean = sMV[0], inv = sMV[1];
    float* ob = out + ((size_t)o*BATCH + b)*16384;
    #pragma unroll 8
    for (int j = 0; j < 64; j++){
        int p = tid + j*256;
        ob[p] = (scn[p] - mean)*inv*lng[p] + lnb[p];
    }
}

// ---------------- launch ----------------
extern "C" void kernel_launch(void* const* d_in, const int* in_sizes, int n_in,
                              void* d_out, int out_size){
    const float *caps=0,*Wt=0,*bt=0,*Wv=0,*bv=0,*Ws=0,*bng=0,*bnb=0,*lng=0,*lnb=0;
    int seen1 = 0, seen16k = 0;
    for (int i = 0; i < n_in; i++){
        const float* p = (const float*)d_in[i];
        switch (in_sizes[i]){
            case 524288: caps = p; break;
            case 147456: Wt = p; break;
            case 1024:   bt = p; break;
            case 2048:   Wv = p; break;
            case 256:    bv = p; break;
            case 54:     Ws = p; break;
            case 1:      if (!seen1){ bng = p; seen1 = 1; } else bnb = p; break;
            case 16384:  if (!seen16k){ lng = p; seen16k = 1; } else lnb = p; break;
            default: break;
        }
    }
    float* out = (float*)d_out;

    cudaFuncSetAttribute(k1_conv2d, cudaFuncAttributeMaxDynamicSharedMemorySize, K1_SMEM);
    cudaFuncSetAttribute(k3_conv3d, cudaFuncAttributeMaxDynamicSharedMemorySize, K3_T*4);
    cudaFuncSetAttribute(k5_final,  cudaFuncAttributeMaxDynamicSharedMemorySize, 16384*4);

    k0_zero<<<1, 32>>>();
    k1_conv2d<<<dim3(8, 8, 32), 256, K1_SMEM>>>(caps, Wt, bt);
    k2_values<<<dim3(64, 8, 32), 256>>>(Wv, bv);
    k3_conv3d<<<dim3(4, 8, 32), 256, K3_T*4>>>(Ws);
    k4_bn<<<1, 32>>>(bng, bnb);
    k5_final<<<dim3(32, 8), 256, 16384*4>>>(lng, lnb, out);
}